// round 5
// baseline (speedup 1.0000x reference)
#include <cuda_runtime.h>
#include <cuda_fp16.h>
#include <cstdint>

// ---------------- problem constants ----------------
#define NWIN    4096
#define NTOK    49
#define HID     384
#define NHEAD   12
#define DHEAD   32
#define MTOT    (NWIN*NTOK)          // 200704
#define QKV_N   (3*HID)              // 1152
#define QSCALE  0.17677669529663687f // 32^-0.5

// ---------------- device scratch (no cudaMalloc allowed) ----------------
__device__ float g_q[(size_t)MTOT * HID];    // [win][head][tok][d]
__device__ float g_k[(size_t)MTOT * HID];
__device__ float g_v[(size_t)MTOT * HID];
__device__ float g_ao[(size_t)MTOT * HID];   // attention output [m][h*32+d]
__device__ float g_bias[NHEAD * NTOK * NTOK];

// ---------------- shared memory layout for GEMM kernels ----------------
struct SmemGemm {
    __half Ah[128 * 40];
    __half Al[128 * 40];
    __half Bh[96 * 40];
    __half Bl[96 * 40];
};                                    // 35840 bytes
union SmemU {
    SmemGemm g;
    float    c[128 * 96];             // 49152 bytes (C staging)
};

// ---------------- mma.sync m16n8k16 fp16 -> fp32 ----------------
__device__ __forceinline__ void mma_f16(float c[4], const uint32_t a[4], const uint32_t b[2]) {
    asm volatile(
        "mma.sync.aligned.m16n8k16.row.col.f32.f16.f16.f32 "
        "{%0,%1,%2,%3}, {%4,%5,%6,%7}, {%8,%9}, {%0,%1,%2,%3};\n"
        : "+f"(c[0]), "+f"(c[1]), "+f"(c[2]), "+f"(c[3])
        : "r"(a[0]), "r"(a[1]), "r"(a[2]), "r"(a[3]),
          "r"(b[0]), "r"(b[1]));
}

__device__ __forceinline__ uint32_t ld_h2(const __half* p) {
    return *reinterpret_cast<const uint32_t*>(p);
}

__device__ __forceinline__ void split_store(__half* hi, __half* lo, float a, float b) {
    __half2 h, l;
    h.x = __float2half_rn(a); l.x = __float2half_rn(a - __half2float(h.x));
    h.y = __float2half_rn(b); l.y = __float2half_rn(b - __half2float(h.y));
    *reinterpret_cast<__half2*>(hi) = h;
    *reinterpret_cast<__half2*>(lo) = l;
}

// ---------------- shared GEMM mainloop: C[128x96] = A[m0:,384] * B[n0:,384]^T ----------------
// fp16 split: exact to ~2^-22. 256 threads, warp grid 4(M)x2(N), warp tile 32x48.
// Software-pipelined: next K-tile is prefetched into registers while MMAs run.
__device__ __forceinline__ void run_gemm(const float* __restrict__ A,
                                         const float* __restrict__ B,
                                         int m0, int n0,
                                         SmemGemm* sm, float acc[2][6][4]) {
    const int tid  = threadIdx.x;
    const int lane = tid & 31;
    const int wid  = tid >> 5;
    const int wm   = wid & 3;
    const int wn   = wid >> 2;
    const int lr   = tid >> 3;          // 0..31
    const int lc   = (tid & 7) << 2;    // 0,4..28

    const float* Abase = A + (size_t)(m0 + lr) * 384 + lc;
    const float* Bbase = B + (size_t)(n0 + lr) * 384 + lc;

    float4 ra[4], rb[3];
    #pragma unroll
    for (int p = 0; p < 4; p++)
        ra[p] = *reinterpret_cast<const float4*>(Abase + (size_t)p * 32 * 384);
    #pragma unroll
    for (int p = 0; p < 3; p++)
        rb[p] = *reinterpret_cast<const float4*>(Bbase + (size_t)p * 32 * 384);

    for (int k0 = 0; k0 < 384; k0 += 32) {
        __syncthreads();
        // store prefetched tile into hi/lo fp16 smem
        #pragma unroll
        for (int p = 0; p < 4; p++) {
            int row = lr + p * 32;
            split_store(&sm->Ah[row * 40 + lc],     &sm->Al[row * 40 + lc],     ra[p].x, ra[p].y);
            split_store(&sm->Ah[row * 40 + lc + 2], &sm->Al[row * 40 + lc + 2], ra[p].z, ra[p].w);
        }
        #pragma unroll
        for (int p = 0; p < 3; p++) {
            int row = lr + p * 32;
            split_store(&sm->Bh[row * 40 + lc],     &sm->Bl[row * 40 + lc],     rb[p].x, rb[p].y);
            split_store(&sm->Bh[row * 40 + lc + 2], &sm->Bl[row * 40 + lc + 2], rb[p].z, rb[p].w);
        }
        __syncthreads();

        // prefetch next K-tile while MMAs execute
        if (k0 + 32 < 384) {
            #pragma unroll
            for (int p = 0; p < 4; p++)
                ra[p] = *reinterpret_cast<const float4*>(Abase + (size_t)p * 32 * 384 + k0 + 32);
            #pragma unroll
            for (int p = 0; p < 3; p++)
                rb[p] = *reinterpret_cast<const float4*>(Bbase + (size_t)p * 32 * 384 + k0 + 32);
        }

        #pragma unroll
        for (int ks = 0; ks < 32; ks += 16) {
            uint32_t ah[2][4], al[2][4], bh[6][2], bl[6][2];
            const int rr = lane >> 2;
            const int cc = ks + ((lane & 3) << 1);
            #pragma unroll
            for (int mt = 0; mt < 2; mt++) {
                int rb2 = wm * 32 + mt * 16 + rr;
                ah[mt][0] = ld_h2(&sm->Ah[rb2 * 40 + cc]);
                ah[mt][1] = ld_h2(&sm->Ah[(rb2 + 8) * 40 + cc]);
                ah[mt][2] = ld_h2(&sm->Ah[rb2 * 40 + cc + 8]);
                ah[mt][3] = ld_h2(&sm->Ah[(rb2 + 8) * 40 + cc + 8]);
                al[mt][0] = ld_h2(&sm->Al[rb2 * 40 + cc]);
                al[mt][1] = ld_h2(&sm->Al[(rb2 + 8) * 40 + cc]);
                al[mt][2] = ld_h2(&sm->Al[rb2 * 40 + cc + 8]);
                al[mt][3] = ld_h2(&sm->Al[(rb2 + 8) * 40 + cc + 8]);
            }
            #pragma unroll
            for (int nt = 0; nt < 6; nt++) {
                int nb = wn * 48 + nt * 8 + rr;
                bh[nt][0] = ld_h2(&sm->Bh[nb * 40 + cc]);
                bh[nt][1] = ld_h2(&sm->Bh[nb * 40 + cc + 8]);
                bl[nt][0] = ld_h2(&sm->Bl[nb * 40 + cc]);
                bl[nt][1] = ld_h2(&sm->Bl[nb * 40 + cc + 8]);
            }
            #pragma unroll
            for (int mt = 0; mt < 2; mt++)
                #pragma unroll
                for (int nt = 0; nt < 6; nt++) {
                    mma_f16(acc[mt][nt], ah[mt], bh[nt]);  // hi*hi
                    mma_f16(acc[mt][nt], ah[mt], bl[nt]);  // hi*lo
                    mma_f16(acc[mt][nt], al[mt], bh[nt]);  // lo*hi
                }
        }
    }
}

// ---------------- K0: dense relative position bias ----------------
__global__ void bias_kernel(const float* __restrict__ table, const int* __restrict__ ridx) {
    int e = blockIdx.x * 256 + threadIdx.x;
    if (e < NHEAD * NTOK * NTOK) {
        int h = e / (NTOK * NTOK);
        int r = e - h * (NTOK * NTOK);
        g_bias[e] = table[ridx[r] * NHEAD + h];
    }
}

// ---------------- K1: QKV projection + scatter ----------------
__global__ void __launch_bounds__(256) qkv_kernel(const float* __restrict__ x,
                                                  const float* __restrict__ qkv_w,
                                                  const float* __restrict__ qkv_b) {
    __shared__ SmemU sm;
    float acc[2][6][4];
    #pragma unroll
    for (int a = 0; a < 2; a++)
        #pragma unroll
        for (int b = 0; b < 6; b++)
            #pragma unroll
            for (int c = 0; c < 4; c++) acc[a][b][c] = 0.f;

    const int n0 = blockIdx.x * 96;   // == head h * 96
    const int m0 = blockIdx.y * 128;
    run_gemm(x, qkv_w, m0, n0, &sm.g, acc);
    __syncthreads();

    // stage C into smem
    const int lane = threadIdx.x & 31, wid = threadIdx.x >> 5;
    const int wm = wid & 3, wn = wid >> 2;
    const int rr = lane >> 2, c2 = (lane & 3) << 1;
    #pragma unroll
    for (int mt = 0; mt < 2; mt++)
        #pragma unroll
        for (int nt = 0; nt < 6; nt++) {
            int row = wm * 32 + mt * 16 + rr;
            int col = wn * 48 + nt * 8 + c2;
            sm.c[row * 96 + col]           = acc[mt][nt][0];
            sm.c[row * 96 + col + 1]       = acc[mt][nt][1];
            sm.c[(row + 8) * 96 + col]     = acc[mt][nt][2];
            sm.c[(row + 8) * 96 + col + 1] = acc[mt][nt][3];
        }
    __syncthreads();

    // scatter: col = dd*3 + s within head h; coalesced over dd
    const int h = blockIdx.x;
    for (int e = threadIdx.x; e < 128 * 96; e += 256) {
        int dd  = e & 31;
        int t2  = e >> 5;          // 0..383
        int s   = t2 % 3;
        int row = t2 / 3;
        int col = dd * 3 + s;
        float val = sm.c[row * 96 + col] + qkv_b[n0 + col];
        int m = m0 + row;
        int ww = m / 49;
        int t  = m - ww * 49;
        size_t o = ((size_t)(ww * NHEAD + h) * NTOK + t) * DHEAD + dd;
        if (s == 0)      g_q[o] = val * QSCALE;
        else if (s == 1) g_k[o] = val;
        else             g_v[o] = val;
    }
}

// ---------------- K2: per-(window,head) attention, fp32 SIMT ----------------
__global__ void __launch_bounds__(128) attn_kernel() {
    const int bid = blockIdx.x;        // w*12 + h
    const int h   = bid % NHEAD;
    const int ww  = bid / NHEAD;

    __shared__ float qs[49 * 36], ks2[49 * 36], vs2[49 * 36];
    __shared__ float sc[49 * 52];

    const int tid = threadIdx.x, lane = tid & 31, wid = tid >> 5;
    const size_t base = (size_t)bid * (NTOK * DHEAD);

    for (int e = tid; e < NTOK * DHEAD; e += 128) {
        int i = e >> 5, dd = e & 31;
        qs[i * 36 + dd]  = g_q[base + e];
        ks2[i * 36 + dd] = g_k[base + e];
        vs2[i * 36 + dd] = g_v[base + e];
    }
    __syncthreads();

    const float* bias = &g_bias[h * (NTOK * NTOK)];

    // fused scores + softmax: one warp per query row
    for (int i = wid; i < NTOK; i += 4) {
        float qreg[32];
        #pragma unroll
        for (int c = 0; c < 32; c += 4) {
            float4 t = *reinterpret_cast<const float4*>(&qs[i * 36 + c]);
            qreg[c] = t.x; qreg[c + 1] = t.y; qreg[c + 2] = t.z; qreg[c + 3] = t.w;
        }
        float s0;
        {
            const float* kr = &ks2[lane * 36];
            float a = 0.f;
            #pragma unroll
            for (int c = 0; c < 32; c += 4) {
                float4 kv = *reinterpret_cast<const float4*>(&kr[c]);
                a += qreg[c] * kv.x + qreg[c + 1] * kv.y + qreg[c + 2] * kv.z + qreg[c + 3] * kv.w;
            }
            s0 = a + bias[i * 49 + lane];
        }
        float s1 = -1e30f;
        const int j1 = 32 + lane;
        if (j1 < 49) {
            const float* kr = &ks2[j1 * 36];
            float a = 0.f;
            #pragma unroll
            for (int c = 0; c < 32; c += 4) {
                float4 kv = *reinterpret_cast<const float4*>(&kr[c]);
                a += qreg[c] * kv.x + qreg[c + 1] * kv.y + qreg[c + 2] * kv.z + qreg[c + 3] * kv.w;
            }
            s1 = a + bias[i * 49 + j1];
        }
        float mx = fmaxf(s0, s1);
        #pragma unroll
        for (int o = 16; o; o >>= 1) mx = fmaxf(mx, __shfl_xor_sync(0xffffffffu, mx, o));
        float p0 = expf(s0 - mx);
        float p1 = (j1 < 49) ? expf(s1 - mx) : 0.f;
        float sum = p0 + p1;
        #pragma unroll
        for (int o = 16; o; o >>= 1) sum += __shfl_xor_sync(0xffffffffu, sum, o);
        float inv = 1.f / sum;
        sc[i * 52 + lane] = p0 * inv;
        if (j1 < 49) sc[i * 52 + j1] = p1 * inv;
    }
    __syncthreads();

    // P @ V : warp per row, lane = d channel
    for (int i = wid; i < NTOK; i += 4) {
        float a = 0.f;
        const float* pr = &sc[i * 52];
        #pragma unroll
        for (int j = 0; j < 48; j += 4) {
            float4 p = *reinterpret_cast<const float4*>(&pr[j]);
            a += p.x * vs2[(j + 0) * 36 + lane];
            a += p.y * vs2[(j + 1) * 36 + lane];
            a += p.z * vs2[(j + 2) * 36 + lane];
            a += p.w * vs2[(j + 3) * 36 + lane];
        }
        a += pr[48] * vs2[48 * 36 + lane];
        g_ao[(size_t)(ww * NTOK + i) * HID + h * DHEAD + lane] = a;
    }
}

// ---------------- K3: output projection ----------------
__global__ void __launch_bounds__(256) fc_kernel(const float* __restrict__ fc_w,
                                                 const float* __restrict__ fc_b,
                                                 float* __restrict__ out) {
    __shared__ SmemU sm;
    float acc[2][6][4];
    #pragma unroll
    for (int a = 0; a < 2; a++)
        #pragma unroll
        for (int b = 0; b < 6; b++)
            #pragma unroll
            for (int c = 0; c < 4; c++) acc[a][b][c] = 0.f;

    const int n0 = blockIdx.x * 96;
    const int m0 = blockIdx.y * 128;
    run_gemm(g_ao, fc_w, m0, n0, &sm.g, acc);

    const int lane = threadIdx.x & 31, wid = threadIdx.x >> 5;
    const int wm = wid & 3, wn = wid >> 2;
    const int rr = lane >> 2, c2 = (lane & 3) << 1;
    #pragma unroll
    for (int mt = 0; mt < 2; mt++)
        #pragma unroll
        for (int nt = 0; nt < 6; nt++) {
            int row = m0 + wm * 32 + mt * 16 + rr;
            int col = n0 + wn * 48 + nt * 8 + c2;
            float b0 = fc_b[col], b1 = fc_b[col + 1];
            float2 v0 = make_float2(acc[mt][nt][0] + b0, acc[mt][nt][1] + b1);
            float2 v1 = make_float2(acc[mt][nt][2] + b0, acc[mt][nt][3] + b1);
            *reinterpret_cast<float2*>(&out[(size_t)row * 384 + col])       = v0;
            *reinterpret_cast<float2*>(&out[(size_t)(row + 8) * 384 + col]) = v1;
        }
}

// ---------------- launch ----------------
extern "C" void kernel_launch(void* const* d_in, const int* in_sizes, int n_in,
                              void* d_out, int out_size) {
    const float* x    = (const float*)d_in[0];
    const float* tbl  = (const float*)d_in[1];
    const float* qw   = (const float*)d_in[2];
    const float* qb   = (const float*)d_in[3];
    const float* fw   = (const float*)d_in[4];
    const float* fb   = (const float*)d_in[5];
    const int*   ridx = (const int*)d_in[6];
    float* out = (float*)d_out;

    bias_kernel<<<(NHEAD * NTOK * NTOK + 255) / 256, 256>>>(tbl, ridx);
    qkv_kernel<<<dim3(NHEAD, MTOT / 128), 256>>>(x, qw, qb);
    attn_kernel<<<NWIN * NHEAD, 128>>>();
    fc_kernel<<<dim3(HID / 96, MTOT / 128), 256>>>(fw, fb, out);
}

// round 6
// speedup vs baseline: 1.1434x; 1.1434x over previous
#include <cuda_runtime.h>
#include <cuda_fp16.h>
#include <cstdint>

// ---------------- problem constants ----------------
#define NWIN    4096
#define NTOK    49
#define HID     384
#define NHEAD   12
#define DHEAD   32
#define MTOT    (NWIN*NTOK)          // 200704
#define QSCALE  0.17677669529663687f // 32^-0.5

// ---------------- device scratch (no cudaMalloc allowed) ----------------
__device__ float g_q[(size_t)MTOT * HID];    // [win][head][tok][d]
__device__ float g_k[(size_t)MTOT * HID];
__device__ float g_v[(size_t)MTOT * HID];
__device__ float g_ao[(size_t)MTOT * HID];   // attention output [m][h*32+d]
__device__ float g_bias[NHEAD * NTOK * NTOK];

// ---------------- shared memory layout for GEMM kernels ----------------
struct SmemGemm {
    __half Ah[128 * 40];
    __half Al[128 * 40];
    __half Bh[96 * 40];
    __half Bl[96 * 40];
};
union SmemU {
    SmemGemm g;
    float    c[128 * 96];
};

// ---------------- mma.sync m16n8k16 fp16 -> fp32 ----------------
__device__ __forceinline__ void mma_f16(float c[4], const uint32_t a[4], const uint32_t b[2]) {
    asm volatile(
        "mma.sync.aligned.m16n8k16.row.col.f32.f16.f16.f32 "
        "{%0,%1,%2,%3}, {%4,%5,%6,%7}, {%8,%9}, {%0,%1,%2,%3};\n"
        : "+f"(c[0]), "+f"(c[1]), "+f"(c[2]), "+f"(c[3])
        : "r"(a[0]), "r"(a[1]), "r"(a[2]), "r"(a[3]),
          "r"(b[0]), "r"(b[1]));
}

__device__ __forceinline__ uint32_t ld_h2(const __half* p) {
    return *reinterpret_cast<const uint32_t*>(p);
}

__device__ __forceinline__ void split_store(__half* hi, __half* lo, float a, float b) {
    __half2 h, l;
    h.x = __float2half_rn(a); l.x = __float2half_rn(a - __half2float(h.x));
    h.y = __float2half_rn(b); l.y = __float2half_rn(b - __half2float(h.y));
    *reinterpret_cast<__half2*>(hi) = h;
    *reinterpret_cast<__half2*>(lo) = l;
}

// ---------------- shared GEMM mainloop (K1/K3): C[128x96] = A * B^T ----------------
__device__ __forceinline__ void run_gemm(const float* __restrict__ A,
                                         const float* __restrict__ B,
                                         int m0, int n0,
                                         SmemGemm* sm, float acc[2][6][4]) {
    const int tid  = threadIdx.x;
    const int lane = tid & 31;
    const int wid  = tid >> 5;
    const int wm   = wid & 3;
    const int wn   = wid >> 2;
    const int lr   = tid >> 3;
    const int lc   = (tid & 7) << 2;

    const float* Abase = A + (size_t)(m0 + lr) * 384 + lc;
    const float* Bbase = B + (size_t)(n0 + lr) * 384 + lc;

    float4 ra[4], rb[3];
    #pragma unroll
    for (int p = 0; p < 4; p++)
        ra[p] = *reinterpret_cast<const float4*>(Abase + (size_t)p * 32 * 384);
    #pragma unroll
    for (int p = 0; p < 3; p++)
        rb[p] = *reinterpret_cast<const float4*>(Bbase + (size_t)p * 32 * 384);

    for (int k0 = 0; k0 < 384; k0 += 32) {
        __syncthreads();
        #pragma unroll
        for (int p = 0; p < 4; p++) {
            int row = lr + p * 32;
            split_store(&sm->Ah[row * 40 + lc],     &sm->Al[row * 40 + lc],     ra[p].x, ra[p].y);
            split_store(&sm->Ah[row * 40 + lc + 2], &sm->Al[row * 40 + lc + 2], ra[p].z, ra[p].w);
        }
        #pragma unroll
        for (int p = 0; p < 3; p++) {
            int row = lr + p * 32;
            split_store(&sm->Bh[row * 40 + lc],     &sm->Bl[row * 40 + lc],     rb[p].x, rb[p].y);
            split_store(&sm->Bh[row * 40 + lc + 2], &sm->Bl[row * 40 + lc + 2], rb[p].z, rb[p].w);
        }
        __syncthreads();

        if (k0 + 32 < 384) {
            #pragma unroll
            for (int p = 0; p < 4; p++)
                ra[p] = *reinterpret_cast<const float4*>(Abase + (size_t)p * 32 * 384 + k0 + 32);
            #pragma unroll
            for (int p = 0; p < 3; p++)
                rb[p] = *reinterpret_cast<const float4*>(Bbase + (size_t)p * 32 * 384 + k0 + 32);
        }

        #pragma unroll
        for (int ks = 0; ks < 32; ks += 16) {
            uint32_t ah[2][4], al[2][4], bh[6][2], bl[6][2];
            const int rr = lane >> 2;
            const int cc = ks + ((lane & 3) << 1);
            #pragma unroll
            for (int mt = 0; mt < 2; mt++) {
                int rb2 = wm * 32 + mt * 16 + rr;
                ah[mt][0] = ld_h2(&sm->Ah[rb2 * 40 + cc]);
                ah[mt][1] = ld_h2(&sm->Ah[(rb2 + 8) * 40 + cc]);
                ah[mt][2] = ld_h2(&sm->Ah[rb2 * 40 + cc + 8]);
                ah[mt][3] = ld_h2(&sm->Ah[(rb2 + 8) * 40 + cc + 8]);
                al[mt][0] = ld_h2(&sm->Al[rb2 * 40 + cc]);
                al[mt][1] = ld_h2(&sm->Al[(rb2 + 8) * 40 + cc]);
                al[mt][2] = ld_h2(&sm->Al[rb2 * 40 + cc + 8]);
                al[mt][3] = ld_h2(&sm->Al[(rb2 + 8) * 40 + cc + 8]);
            }
            #pragma unroll
            for (int nt = 0; nt < 6; nt++) {
                int nb = wn * 48 + nt * 8 + rr;
                bh[nt][0] = ld_h2(&sm->Bh[nb * 40 + cc]);
                bh[nt][1] = ld_h2(&sm->Bh[nb * 40 + cc + 8]);
                bl[nt][0] = ld_h2(&sm->Bl[nb * 40 + cc]);
                bl[nt][1] = ld_h2(&sm->Bl[nb * 40 + cc + 8]);
            }
            #pragma unroll
            for (int mt = 0; mt < 2; mt++)
                #pragma unroll
                for (int nt = 0; nt < 6; nt++) {
                    mma_f16(acc[mt][nt], ah[mt], bh[nt]);
                    mma_f16(acc[mt][nt], ah[mt], bl[nt]);
                    mma_f16(acc[mt][nt], al[mt], bh[nt]);
                }
        }
    }
}

// ---------------- K0: dense relative position bias ----------------
__global__ void bias_kernel(const float* __restrict__ table, const int* __restrict__ ridx) {
    int e = blockIdx.x * 256 + threadIdx.x;
    if (e < NHEAD * NTOK * NTOK) {
        int h = e / (NTOK * NTOK);
        int r = e - h * (NTOK * NTOK);
        g_bias[e] = table[ridx[r] * NHEAD + h];
    }
}

// ---------------- K1: QKV projection + scatter ----------------
__global__ void __launch_bounds__(256) qkv_kernel(const float* __restrict__ x,
                                                  const float* __restrict__ qkv_w,
                                                  const float* __restrict__ qkv_b) {
    __shared__ SmemU sm;
    float acc[2][6][4];
    #pragma unroll
    for (int a = 0; a < 2; a++)
        #pragma unroll
        for (int b = 0; b < 6; b++)
            #pragma unroll
            for (int c = 0; c < 4; c++) acc[a][b][c] = 0.f;

    const int n0 = blockIdx.x * 96;
    const int m0 = blockIdx.y * 128;
    run_gemm(x, qkv_w, m0, n0, &sm.g, acc);
    __syncthreads();

    const int lane = threadIdx.x & 31, wid = threadIdx.x >> 5;
    const int wm = wid & 3, wn = wid >> 2;
    const int rr = lane >> 2, c2 = (lane & 3) << 1;
    #pragma unroll
    for (int mt = 0; mt < 2; mt++)
        #pragma unroll
        for (int nt = 0; nt < 6; nt++) {
            int row = wm * 32 + mt * 16 + rr;
            int col = wn * 48 + nt * 8 + c2;
            sm.c[row * 96 + col]           = acc[mt][nt][0];
            sm.c[row * 96 + col + 1]       = acc[mt][nt][1];
            sm.c[(row + 8) * 96 + col]     = acc[mt][nt][2];
            sm.c[(row + 8) * 96 + col + 1] = acc[mt][nt][3];
        }
    __syncthreads();

    const int h = blockIdx.x;
    for (int e = threadIdx.x; e < 128 * 96; e += 256) {
        int dd  = e & 31;
        int t2  = e >> 5;
        int s   = t2 % 3;
        int row = t2 / 3;
        int col = dd * 3 + s;
        float val = sm.c[row * 96 + col] + qkv_b[n0 + col];
        int m = m0 + row;
        int ww = m / 49;
        int t  = m - ww * 49;
        size_t o = ((size_t)(ww * NHEAD + h) * NTOK + t) * DHEAD + dd;
        if (s == 0)      g_q[o] = val * QSCALE;
        else if (s == 1) g_k[o] = val;
        else             g_v[o] = val;
    }
}

// ---------------- K2: per-(window,head) attention via fp16-split MMA ----------------
// M pad 64 (queries), key dim pad 64 (K rows 49..63 zeroed), d = 32.
struct AttnSmem {
    union {
        struct {
            __half Qh[64 * 40];   // 5120 B
            __half Ql[64 * 40];
            __half Kh[64 * 40];
            __half Kl[64 * 40];
        } qk;                      // 20480 B
        struct {
            __half Ph[64 * 72];   // 9216 B
            __half Pl[64 * 72];
        } p;                       // 18432 B  (alive only after qk is dead)
    } u;
    __half Vth[32 * 72];          // V transposed [d][j], hi
    __half Vtl[32 * 72];          // lo                       (9216 B total)
    float  sc[64 * 57];           // raw scores               (14592 B)
};                                 // ~44.3 KB

__global__ void __launch_bounds__(128) attn_kernel() {
    const int bid = blockIdx.x;        // ww*NHEAD + h
    const int h   = bid % NHEAD;
    const int ww  = bid / NHEAD;

    __shared__ AttnSmem s;

    const int tid = threadIdx.x, lane = tid & 31, wm = tid >> 5;
    const int rr  = lane >> 2;
    const int qoff = (lane & 3) << 1;
    const size_t base = (size_t)bid * (NTOK * DHEAD);

    // zero Q/K (incl. pad rows) and Vt (incl. pad cols): first 20480+9216 bytes
    {
        uint4* z = reinterpret_cast<uint4*>(&s);
        const int nz = (20480 + 9216) / 16;
        for (int i = tid; i < nz; i += 128) z[i] = make_uint4(0, 0, 0, 0);
    }
    __syncthreads();

    // load q/k/v fp32 -> split fp16 smem (1568 floats each = 392 float4)
    for (int e = tid; e < 392; e += 128) {
        int j = e >> 3;               // token 0..48
        int c = (e & 7) << 2;         // d 0,4..28
        float4 q4 = *reinterpret_cast<const float4*>(g_q + base + (size_t)e * 4);
        float4 k4 = *reinterpret_cast<const float4*>(g_k + base + (size_t)e * 4);
        float4 v4 = *reinterpret_cast<const float4*>(g_v + base + (size_t)e * 4);
        split_store(&s.u.qk.Qh[j * 40 + c],     &s.u.qk.Ql[j * 40 + c],     q4.x, q4.y);
        split_store(&s.u.qk.Qh[j * 40 + c + 2], &s.u.qk.Ql[j * 40 + c + 2], q4.z, q4.w);
        split_store(&s.u.qk.Kh[j * 40 + c],     &s.u.qk.Kl[j * 40 + c],     k4.x, k4.y);
        split_store(&s.u.qk.Kh[j * 40 + c + 2], &s.u.qk.Kl[j * 40 + c + 2], k4.z, k4.w);
        const float* vv = &v4.x;
        #pragma unroll
        for (int l = 0; l < 4; l++) {
            float val = vv[l];
            __half hi = __float2half_rn(val);
            __half lo = __float2half_rn(val - __half2float(hi));
            s.Vth[(c + l) * 72 + j] = hi;
            s.Vtl[(c + l) * 72 + j] = lo;
        }
    }
    __syncthreads();

    // ---- scores: S[64x56] = Q @ K^T (warp wm owns rows wm*16..+15) ----
    {
        float acc[7][4];
        #pragma unroll
        for (int nt = 0; nt < 7; nt++)
            #pragma unroll
            for (int c = 0; c < 4; c++) acc[nt][c] = 0.f;

        #pragma unroll
        for (int kt = 0; kt < 32; kt += 16) {
            uint32_t ah[4], al[4];
            const int rb = wm * 16 + rr;
            const int cc = kt + qoff;
            ah[0] = ld_h2(&s.u.qk.Qh[rb * 40 + cc]);
            ah[1] = ld_h2(&s.u.qk.Qh[(rb + 8) * 40 + cc]);
            ah[2] = ld_h2(&s.u.qk.Qh[rb * 40 + cc + 8]);
            ah[3] = ld_h2(&s.u.qk.Qh[(rb + 8) * 40 + cc + 8]);
            al[0] = ld_h2(&s.u.qk.Ql[rb * 40 + cc]);
            al[1] = ld_h2(&s.u.qk.Ql[(rb + 8) * 40 + cc]);
            al[2] = ld_h2(&s.u.qk.Ql[rb * 40 + cc + 8]);
            al[3] = ld_h2(&s.u.qk.Ql[(rb + 8) * 40 + cc + 8]);
            #pragma unroll
            for (int nt = 0; nt < 7; nt++) {
                const int nb = nt * 8 + rr;
                uint32_t bh[2], bl[2];
                bh[0] = ld_h2(&s.u.qk.Kh[nb * 40 + cc]);
                bh[1] = ld_h2(&s.u.qk.Kh[nb * 40 + cc + 8]);
                bl[0] = ld_h2(&s.u.qk.Kl[nb * 40 + cc]);
                bl[1] = ld_h2(&s.u.qk.Kl[nb * 40 + cc + 8]);
                mma_f16(acc[nt], ah, bh);
                mma_f16(acc[nt], ah, bl);
                mma_f16(acc[nt], al, bh);
            }
        }
        // write raw scores to smem
        const int r0 = wm * 16 + rr;
        #pragma unroll
        for (int nt = 0; nt < 7; nt++) {
            const int c = nt * 8 + qoff;
            s.sc[r0 * 57 + c]           = acc[nt][0];
            s.sc[r0 * 57 + c + 1]       = acc[nt][1];
            s.sc[(r0 + 8) * 57 + c]     = acc[nt][2];
            s.sc[(r0 + 8) * 57 + c + 1] = acc[nt][3];
        }
    }
    __syncthreads();

    // ---- softmax (+bias) rows, write P split fp16 into union (Q/K dead) ----
    const float* bias = &g_bias[h * (NTOK * NTOK)];
    for (int i = wm; i < NTOK; i += 4) {
        const int j2 = 32 + lane;
        const bool v2 = (j2 < NTOK);
        float s0 = s.sc[i * 57 + lane] + bias[i * 49 + lane];
        float s1 = v2 ? (s.sc[i * 57 + j2] + bias[i * 49 + j2]) : -3.0e38f;
        float mx = fmaxf(s0, s1);
        #pragma unroll
        for (int o = 16; o; o >>= 1) mx = fmaxf(mx, __shfl_xor_sync(0xffffffffu, mx, o));
        float p0 = expf(s0 - mx);
        float p1 = v2 ? expf(s1 - mx) : 0.f;
        float sum = p0 + p1;
        #pragma unroll
        for (int o = 16; o; o >>= 1) sum += __shfl_xor_sync(0xffffffffu, sum, o);
        float inv = 1.f / sum;
        p0 *= inv;
        p1 = v2 ? p1 * inv : 0.f;
        // split-store P (cols 49..63 get exact zeros)
        {
            __half hi = __float2half_rn(p0);
            __half lo = __float2half_rn(p0 - __half2float(hi));
            s.u.p.Ph[i * 72 + lane] = hi;
            s.u.p.Pl[i * 72 + lane] = lo;
            __half hi1 = __float2half_rn(p1);
            __half lo1 = __float2half_rn(p1 - __half2float(hi1));
            s.u.p.Ph[i * 72 + j2] = hi1;
            s.u.p.Pl[i * 72 + j2] = lo1;
        }
    }
    __syncthreads();

    // ---- PV: O[64x32] = P[64x64] @ V[64x32]  (Vt is col-major B) ----
    {
        float acc[4][4];
        #pragma unroll
        for (int nt = 0; nt < 4; nt++)
            #pragma unroll
            for (int c = 0; c < 4; c++) acc[nt][c] = 0.f;

        #pragma unroll
        for (int kt = 0; kt < 64; kt += 16) {
            uint32_t ah[4], al[4];
            const int rb = wm * 16 + rr;
            const int cc = kt + qoff;
            ah[0] = ld_h2(&s.u.p.Ph[rb * 72 + cc]);
            ah[1] = ld_h2(&s.u.p.Ph[(rb + 8) * 72 + cc]);
            ah[2] = ld_h2(&s.u.p.Ph[rb * 72 + cc + 8]);
            ah[3] = ld_h2(&s.u.p.Ph[(rb + 8) * 72 + cc + 8]);
            al[0] = ld_h2(&s.u.p.Pl[rb * 72 + cc]);
            al[1] = ld_h2(&s.u.p.Pl[(rb + 8) * 72 + cc]);
            al[2] = ld_h2(&s.u.p.Pl[rb * 72 + cc + 8]);
            al[3] = ld_h2(&s.u.p.Pl[(rb + 8) * 72 + cc + 8]);
            #pragma unroll
            for (int nt = 0; nt < 4; nt++) {
                const int nb = nt * 8 + rr;
                uint32_t bh[2], bl[2];
                bh[0] = ld_h2(&s.Vth[nb * 72 + cc]);
                bh[1] = ld_h2(&s.Vth[nb * 72 + cc + 8]);
                bl[0] = ld_h2(&s.Vtl[nb * 72 + cc]);
                bl[1] = ld_h2(&s.Vtl[nb * 72 + cc + 8]);
                mma_f16(acc[nt], ah, bh);
                mma_f16(acc[nt], ah, bl);
                mma_f16(acc[nt], al, bh);
            }
        }
        // epilogue: rows < 49 to g_ao[(ww*49+m)*384 + h*32 + d]
        const int r0 = wm * 16 + rr;
        #pragma unroll
        for (int nt = 0; nt < 4; nt++) {
            const int d = nt * 8 + qoff;
            if (r0 < NTOK) {
                float2 v = make_float2(acc[nt][0], acc[nt][1]);
                *reinterpret_cast<float2*>(&g_ao[((size_t)ww * NTOK + r0) * HID + h * DHEAD + d]) = v;
            }
            if (r0 + 8 < NTOK) {
                float2 v = make_float2(acc[nt][2], acc[nt][3]);
                *reinterpret_cast<float2*>(&g_ao[((size_t)ww * NTOK + r0 + 8) * HID + h * DHEAD + d]) = v;
            }
        }
    }
}

// ---------------- K3: output projection ----------------
__global__ void __launch_bounds__(256) fc_kernel(const float* __restrict__ fc_w,
                                                 const float* __restrict__ fc_b,
                                                 float* __restrict__ out) {
    __shared__ SmemU sm;
    float acc[2][6][4];
    #pragma unroll
    for (int a = 0; a < 2; a++)
        #pragma unroll
        for (int b = 0; b < 6; b++)
            #pragma unroll
            for (int c = 0; c < 4; c++) acc[a][b][c] = 0.f;

    const int n0 = blockIdx.x * 96;
    const int m0 = blockIdx.y * 128;
    run_gemm(g_ao, fc_w, m0, n0, &sm.g, acc);

    const int lane = threadIdx.x & 31, wid = threadIdx.x >> 5;
    const int wm = wid & 3, wn = wid >> 2;
    const int rr = lane >> 2, c2 = (lane & 3) << 1;
    #pragma unroll
    for (int mt = 0; mt < 2; mt++)
        #pragma unroll
        for (int nt = 0; nt < 6; nt++) {
            int row = m0 + wm * 32 + mt * 16 + rr;
            int col = n0 + wn * 48 + nt * 8 + c2;
            float b0 = fc_b[col], b1 = fc_b[col + 1];
            float2 v0 = make_float2(acc[mt][nt][0] + b0, acc[mt][nt][1] + b1);
            float2 v1 = make_float2(acc[mt][nt][2] + b0, acc[mt][nt][3] + b1);
            *reinterpret_cast<float2*>(&out[(size_t)row * 384 + col])       = v0;
            *reinterpret_cast<float2*>(&out[(size_t)(row + 8) * 384 + col]) = v1;
        }
}

// ---------------- launch ----------------
extern "C" void kernel_launch(void* const* d_in, const int* in_sizes, int n_in,
                              void* d_out, int out_size) {
    const float* x    = (const float*)d_in[0];
    const float* tbl  = (const float*)d_in[1];
    const float* qw   = (const float*)d_in[2];
    const float* qb   = (const float*)d_in[3];
    const float* fw   = (const float*)d_in[4];
    const float* fb   = (const float*)d_in[5];
    const int*   ridx = (const int*)d_in[6];
    float* out = (float*)d_out;

    bias_kernel<<<(NHEAD * NTOK * NTOK + 255) / 256, 256>>>(tbl, ridx);
    qkv_kernel<<<dim3(NHEAD, MTOT / 128), 256>>>(x, qw, qb);
    attn_kernel<<<NWIN * NHEAD, 128>>>();
    fc_kernel<<<dim3(HID / 96, MTOT / 128), 256>>>(fw, fb, out);
}